// round 1
// baseline (speedup 1.0000x reference)
#include <cuda_runtime.h>
#include <math.h>

// Problem constants (fixed by the dataset problem)
#define BATCH 8
#define NN    2048
#define CC    256
#define NGRP  4
#define NGROUPS (CC / NGRP)   // 64
#define RANK  16
#define QSTEPS 8
#define EPS_SPHERE 1e-6f
#define EPS_GN     1e-5f

// Scratch (device globals — no allocation allowed)
__device__ float g_K [(size_t)BATCH * NN * NN];   // 134 MB coupling matrix
__device__ float g_ys[(size_t)BATCH * NN * CC];   // sphere(GN(y)^T)
__device__ float g_x0[(size_t)BATCH * NN * CC];   // sphere(x)

// ---------------------------------------------------------------------------
// Kernel 1: K[b,n,m] = 0.5*(sc[b,n,m] + sc[b,m,n]) * sigmoid(U[n]·U[m])
// grid (64,64), block (32,32). Sigmoid computed once per (n,m), reused for all b.
// ---------------------------------------------------------------------------
__global__ __launch_bounds__(1024) void prep_K(const float* __restrict__ sc,
                                               const float* __restrict__ U)
{
    __shared__ float Un[32][17];
    __shared__ float Um[32][17];
    __shared__ float tT[32][33];

    const int tx = threadIdx.x, ty = threadIdx.y;
    const int n0 = blockIdx.y * 32, m0 = blockIdx.x * 32;
    const int t = ty * 32 + tx;

    if (t < 512) {
        Un[t >> 4][t & 15] = U[(n0 + (t >> 4)) * RANK + (t & 15)];
    } else {
        int u = t - 512;
        Um[u >> 4][u & 15] = U[(m0 + (u >> 4)) * RANK + (u & 15)];
    }
    __syncthreads();

    float d = 0.f;
#pragma unroll
    for (int k = 0; k < RANK; k++) d += Un[ty][k] * Um[tx][k];
    const float a = 1.f / (1.f + __expf(-d));

    const int n = n0 + ty, m = m0 + tx;
#pragma unroll 1
    for (int b = 0; b < BATCH; b++) {
        const size_t base = (size_t)b * NN * NN;
        // coalesced read of the transposed tile
        tT[ty][tx] = sc[base + (size_t)(m0 + ty) * NN + (n0 + tx)];
        __syncthreads();
        const float scT = tT[tx][ty];
        const float v = 0.5f * (sc[base + (size_t)n * NN + m] + scT) * a;
        g_K[base + (size_t)n * NN + m] = v;
        __syncthreads();
    }
}

// ---------------------------------------------------------------------------
// Kernel 2: GroupNorm over (4 channels x 2048) per (b,g), then transpose to
// [B,N,C] and sphere-normalize each 4-vector (GN groups == sphere groups).
// grid = B*64 blocks, 256 threads.
// ---------------------------------------------------------------------------
__global__ __launch_bounds__(256) void gn_sphere(const float* __restrict__ y,
                                                 const float* __restrict__ gw,
                                                 const float* __restrict__ gb)
{
    const int b = blockIdx.x >> 6;
    const int g = blockIdx.x & 63;
    const float* yg = y + ((size_t)b * CC + g * NGRP) * NN; // 4*2048 contiguous
    const int tid = threadIdx.x;

    float s = 0.f, s2 = 0.f;
    for (int i = tid; i < NGRP * NN; i += 256) {
        float v = yg[i];
        s += v; s2 += v * v;
    }
    __shared__ float shs[8], shs2[8];
#pragma unroll
    for (int o = 16; o; o >>= 1) {
        s  += __shfl_down_sync(0xffffffffu, s,  o);
        s2 += __shfl_down_sync(0xffffffffu, s2, o);
    }
    if ((tid & 31) == 0) { shs[tid >> 5] = s; shs2[tid >> 5] = s2; }
    __syncthreads();
    if (tid == 0) {
        float ts = 0.f, ts2 = 0.f;
#pragma unroll
        for (int i = 0; i < 8; i++) { ts += shs[i]; ts2 += shs2[i]; }
        shs[0] = ts; shs2[0] = ts2;
    }
    __syncthreads();
    const float mu   = shs[0] * (1.f / (NGRP * NN));
    const float var  = shs2[0] * (1.f / (NGRP * NN)) - mu * mu;
    const float rstd = rsqrtf(var + EPS_GN);

    float w[4], bb[4];
#pragma unroll
    for (int j = 0; j < 4; j++) { w[j] = gw[g * 4 + j]; bb[j] = gb[g * 4 + j]; }

    for (int n = tid; n < NN; n += 256) {
        float v[4];
#pragma unroll
        for (int j = 0; j < 4; j++)
            v[j] = (yg[j * NN + n] - mu) * rstd * w[j] + bb[j];
        float n2 = fmaxf(v[0]*v[0] + v[1]*v[1] + v[2]*v[2] + v[3]*v[3], EPS_SPHERE);
        float r = rsqrtf(n2);
        float4 o = make_float4(v[0]*r, v[1]*r, v[2]*r, v[3]*r);
        *(float4*)&g_ys[((size_t)b * NN + n) * CC + g * 4] = o;
    }
}

// ---------------------------------------------------------------------------
// Kernel 3: x0 = sphere(x). One thread per 4-channel group.
// ---------------------------------------------------------------------------
__global__ __launch_bounds__(256) void sphere_x0(const float* __restrict__ x)
{
    int idx = blockIdx.x * blockDim.x + threadIdx.x;
    if (idx >= BATCH * NN * NGROUPS) return;
    float4 v = ((const float4*)x)[idx];
    float n2 = fmaxf(v.x*v.x + v.y*v.y + v.z*v.z + v.w*v.w, EPS_SPHERE);
    float r = rsqrtf(n2);
    ((float4*)g_x0)[idx] = make_float4(v.x*r, v.y*r, v.z*r, v.w*r);
}

// ---------------------------------------------------------------------------
// Kernel 4: one Kuramoto step.
// coupling = K[b] @ xc[b]  (M=2048, Kdim=2048, Ncols=256), fused epilogue:
//   force = coupling + ys; sim = <xc, force>_grp; proj = force - sim*xc;
//   om = pairwise rotation; xn = sphere(xc + gamma*(om + proj))
// Tiling: BM=128, BN=64, BK=16, 256 threads, per-thread micro 8x4 (one group).
// ---------------------------------------------------------------------------
#define BM 128
#define BN 64
#define BK 16

__global__ __launch_bounds__(256) void step_kernel(const float* __restrict__ xc_in,
                                                   float* __restrict__ xout,
                                                   const float* __restrict__ omega,
                                                   const float* __restrict__ gammap)
{
    const int b    = blockIdx.z;
    const int row0 = blockIdx.y * BM;
    const int c0   = blockIdx.x * BN;

    const float* __restrict__ Kb = g_K + (size_t)b * NN * NN;
    const float* __restrict__ Xb = (xc_in ? xc_in : g_x0) + (size_t)b * NN * CC;

    __shared__ float As[BK][BM + 4];   // k-major A tile, padded
    __shared__ float Bs[BK][BN];

    const int tid = threadIdx.x;
    const int mi = tid >> 4;   // 0..15 -> 8 rows each
    const int ni = tid & 15;   // 0..15 -> 4 cols each (one osc group)

    float acc[8][4];
#pragma unroll
    for (int i = 0; i < 8; i++)
#pragma unroll
        for (int j = 0; j < 4; j++) acc[i][j] = 0.f;

    const int arow = tid >> 2;        // 0..63 (two passes cover 128 rows)
    const int acol = (tid & 3) * 4;   // k offset {0,4,8,12}
    const int brow = tid >> 4;        // 0..15
    const int bcol = (tid & 15) * 4;  // 0..60

    for (int k0 = 0; k0 < NN; k0 += BK) {
#pragma unroll
        for (int r = 0; r < 2; r++) {
            const int rr = arow + r * 64;
            float4 av = *(const float4*)&Kb[(size_t)(row0 + rr) * NN + k0 + acol];
            As[acol + 0][rr] = av.x;
            As[acol + 1][rr] = av.y;
            As[acol + 2][rr] = av.z;
            As[acol + 3][rr] = av.w;
        }
        {
            float4 bv = *(const float4*)&Xb[(size_t)(k0 + brow) * CC + c0 + bcol];
            *(float4*)&Bs[brow][bcol] = bv;
        }
        __syncthreads();

#pragma unroll
        for (int k = 0; k < BK; k++) {
            float a[8], bv[4];
            *(float4*)&a[0] = *(const float4*)&As[k][mi * 8];
            *(float4*)&a[4] = *(const float4*)&As[k][mi * 8 + 4];
            *(float4*)&bv[0] = *(const float4*)&Bs[k][ni * 4];
#pragma unroll
            for (int i = 0; i < 8; i++)
#pragma unroll
                for (int j = 0; j < 4; j++)
                    acc[i][j] = fmaf(a[i], bv[j], acc[i][j]);
        }
        __syncthreads();
    }

    // Epilogue (per-thread: 8 rows x one oscillator group of 4 channels)
    const float gamma = *gammap;
    const int c = c0 + ni * 4;
    const float og0 = fabsf(omega[(c >> 1) + 0]);
    const float og1 = fabsf(omega[(c >> 1) + 1]);
    const float* __restrict__ Yb = g_ys + (size_t)b * NN * CC;
    float* __restrict__ Ob = xout + (size_t)b * NN * CC;

#pragma unroll
    for (int i = 0; i < 8; i++) {
        const int r = row0 + mi * 8 + i;
        float4 xv = *(const float4*)&Xb[(size_t)r * CC + c];
        float4 yv = *(const float4*)&Yb[(size_t)r * CC + c];
        float f0 = acc[i][0] + yv.x;
        float f1 = acc[i][1] + yv.y;
        float f2 = acc[i][2] + yv.z;
        float f3 = acc[i][3] + yv.w;
        float sim = xv.x * f0 + xv.y * f1 + xv.z * f2 + xv.w * f3;
        // dxdt = omega(x) + (force - sim*x)
        float d0 =  og0 * xv.y + (f0 - sim * xv.x);
        float d1 = -og0 * xv.x + (f1 - sim * xv.y);
        float d2 =  og1 * xv.w + (f2 - sim * xv.z);
        float d3 = -og1 * xv.z + (f3 - sim * xv.w);
        float u0 = xv.x + gamma * d0;
        float u1 = xv.y + gamma * d1;
        float u2 = xv.z + gamma * d2;
        float u3 = xv.w + gamma * d3;
        float n2 = fmaxf(u0*u0 + u1*u1 + u2*u2 + u3*u3, EPS_SPHERE);
        float rr = rsqrtf(n2);
        *(float4*)&Ob[(size_t)r * CC + c] = make_float4(u0*rr, u1*rr, u2*rr, u3*rr);
    }
}

// ---------------------------------------------------------------------------
// Launch. Inputs (metadata order): x, y, sc, U, omega_param, gn_w, gn_b, gamma, Q
// Output: xs [Q=8, B, N, C] fp32. Q is a host-side loop bound (fixed at 8).
// ---------------------------------------------------------------------------
extern "C" void kernel_launch(void* const* d_in, const int* in_sizes, int n_in,
                              void* d_out, int out_size)
{
    const float* x     = (const float*)d_in[0];
    const float* y     = (const float*)d_in[1];
    const float* sc    = (const float*)d_in[2];
    const float* U     = (const float*)d_in[3];
    const float* omega = (const float*)d_in[4];
    const float* gw    = (const float*)d_in[5];
    const float* gb    = (const float*)d_in[6];
    const float* gamma = (const float*)d_in[7];
    float* out = (float*)d_out;

    prep_K<<<dim3(NN / 32, NN / 32), dim3(32, 32)>>>(sc, U);
    gn_sphere<<<BATCH * NGROUPS, 256>>>(y, gw, gb);
    sphere_x0<<<(BATCH * NN * NGROUPS + 255) / 256, 256>>>(x);

    const size_t step_elems = (size_t)BATCH * NN * CC;
    for (int q = 0; q < QSTEPS; q++) {
        const float* xc = (q == 0) ? nullptr : out + (size_t)(q - 1) * step_elems;
        step_kernel<<<dim3(CC / BN, NN / BM, BATCH), 256>>>(
            xc, out + (size_t)q * step_elems, omega, gamma);
    }
}

// round 3
// speedup vs baseline: 3.2945x; 3.2945x over previous
#include <cuda_runtime.h>
#include <cuda_fp16.h>
#include <cstdint>
#include <math.h>

#define BATCH 8
#define NN    2048
#define CC    256
#define RANK  16
#define QSTEPS 8
#define EPS_SPHERE 1e-6f
#define EPS_GN     1e-5f

// ---------------- device scratch (no allocation allowed) ----------------
__device__ __half g_Khi[(size_t)BATCH * NN * NN];   // 67 MB
__device__ __half g_Klo[(size_t)BATCH * NN * NN];   // 67 MB
__device__ __half g_xh [(size_t)BATCH * NN * CC];   // x (fp16 hi), [B,N,C]
__device__ __half g_xl [(size_t)BATCH * NN * CC];   // x (fp16 lo), [B,N,C]
__device__ float  g_ys [(size_t)BATCH * NN * CC];
__device__ float  g_x0 [(size_t)BATCH * NN * CC];

// ---------------- helpers ----------------
__device__ __forceinline__ uint32_t smem_u32(const void* p) {
    uint32_t a;
    asm("{ .reg .u64 t; cvta.to.shared.u64 t, %1; cvt.u32.u64 %0, t; }" : "=r"(a) : "l"(p));
    return a;
}
__device__ __forceinline__ void cp16(uint32_t dst, const void* src) {
    asm volatile("cp.async.cg.shared.global [%0], [%1], 16;" :: "r"(dst), "l"(src));
}
#define CP_COMMIT() asm volatile("cp.async.commit_group;" ::: "memory")
#define CP_WAIT(n)  asm volatile("cp.async.wait_group %0;" :: "n"(n) : "memory")

#define LDSM_X4(r0,r1,r2,r3, a) \
    asm volatile("ldmatrix.sync.aligned.m8n8.x4.shared.b16 {%0,%1,%2,%3}, [%4];" \
        : "=r"(r0), "=r"(r1), "=r"(r2), "=r"(r3) : "r"(a))
#define LDSM_X4T(r0,r1,r2,r3, a) \
    asm volatile("ldmatrix.sync.aligned.m8n8.x4.trans.shared.b16 {%0,%1,%2,%3}, [%4];" \
        : "=r"(r0), "=r"(r1), "=r"(r2), "=r"(r3) : "r"(a))

#define MMA16816(d, a0,a1,a2,a3, b0,b1) \
    asm volatile("mma.sync.aligned.m16n8k16.row.col.f32.f16.f16.f32 " \
        "{%0,%1,%2,%3}, {%4,%5,%6,%7}, {%8,%9}, {%0,%1,%2,%3};" \
        : "+f"((d)[0]), "+f"((d)[1]), "+f"((d)[2]), "+f"((d)[3]) \
        : "r"(a0), "r"(a1), "r"(a2), "r"(a3), "r"(b0), "r"(b1))

// ---------------------------------------------------------------------------
// prep_K: K[b,n,m] = 0.5*(sc[b,n,m]+sc[b,m,n]) * sigmoid(U[n]·U[m]); symmetric,
// so each block (m0 >= n0) writes both triangles, split into fp16 hi/lo.
// ---------------------------------------------------------------------------
__global__ __launch_bounds__(1024) void prep_K(const float* __restrict__ sc,
                                               const float* __restrict__ U)
{
    const int n0 = blockIdx.y * 32, m0 = blockIdx.x * 32;
    if (m0 < n0) return;

    __shared__ float Un[32][17];
    __shared__ float Um[32][17];
    __shared__ float tT[32][33];
    __shared__ float vS[32][33];

    const int tx = threadIdx.x, ty = threadIdx.y;
    const int t = ty * 32 + tx;

    if (t < 512)      Un[t >> 4][t & 15] = U[(n0 + (t >> 4)) * RANK + (t & 15)];
    else { int u = t - 512; Um[u >> 4][u & 15] = U[(m0 + (u >> 4)) * RANK + (u & 15)]; }
    __syncthreads();

    float d = 0.f;
#pragma unroll
    for (int k = 0; k < RANK; k++) d += Un[ty][k] * Um[tx][k];
    const float a = 1.f / (1.f + __expf(-d));

    const int n = n0 + ty, m = m0 + tx;
#pragma unroll 1
    for (int b = 0; b < BATCH; b++) {
        const size_t base = (size_t)b * NN * NN;
        tT[ty][tx] = sc[base + (size_t)(m0 + ty) * NN + (n0 + tx)];
        __syncthreads();
        const float v = 0.5f * (sc[base + (size_t)n * NN + m] + tT[tx][ty]) * a;
        __half hi = __float2half_rn(v);
        __half lo = __float2half_rn(v - __half2float(hi));
        const size_t o1 = base + (size_t)n * NN + m;
        g_Khi[o1] = hi; g_Klo[o1] = lo;
        vS[ty][tx] = v;
        __syncthreads();
        if (m0 != n0) {
            const float vt = vS[tx][ty];
            __half hi2 = __float2half_rn(vt);
            __half lo2 = __float2half_rn(vt - __half2float(hi2));
            const size_t o2 = base + (size_t)(m0 + ty) * NN + (n0 + tx);
            g_Khi[o2] = hi2; g_Klo[o2] = lo2;
        }
        __syncthreads();
    }
}

// ---------------------------------------------------------------------------
// gn_sphere: GroupNorm over (4ch x 2048) per (b,g) then transpose + sphere.
// ---------------------------------------------------------------------------
__global__ __launch_bounds__(256) void gn_sphere(const float* __restrict__ y,
                                                 const float* __restrict__ gw,
                                                 const float* __restrict__ gb)
{
    const int b = blockIdx.x >> 6;
    const int g = blockIdx.x & 63;
    const float* yg = y + ((size_t)b * CC + g * 4) * NN;
    const int tid = threadIdx.x;

    float s = 0.f, s2 = 0.f;
    for (int i = tid; i < 4 * NN; i += 256) { float v = yg[i]; s += v; s2 += v * v; }
    __shared__ float shs[8], shs2[8];
#pragma unroll
    for (int o = 16; o; o >>= 1) {
        s  += __shfl_down_sync(0xffffffffu, s,  o);
        s2 += __shfl_down_sync(0xffffffffu, s2, o);
    }
    if ((tid & 31) == 0) { shs[tid >> 5] = s; shs2[tid >> 5] = s2; }
    __syncthreads();
    if (tid == 0) {
        float ts = 0.f, ts2 = 0.f;
#pragma unroll
        for (int i = 0; i < 8; i++) { ts += shs[i]; ts2 += shs2[i]; }
        shs[0] = ts; shs2[0] = ts2;
    }
    __syncthreads();
    const float mu   = shs[0] * (1.f / (4 * NN));
    const float var  = shs2[0] * (1.f / (4 * NN)) - mu * mu;
    const float rstd = rsqrtf(var + EPS_GN);

    float w[4], bb[4];
#pragma unroll
    for (int j = 0; j < 4; j++) { w[j] = gw[g * 4 + j]; bb[j] = gb[g * 4 + j]; }

    for (int n = tid; n < NN; n += 256) {
        float v[4];
#pragma unroll
        for (int j = 0; j < 4; j++)
            v[j] = (yg[j * NN + n] - mu) * rstd * w[j] + bb[j];
        float n2 = fmaxf(v[0]*v[0] + v[1]*v[1] + v[2]*v[2] + v[3]*v[3], EPS_SPHERE);
        float r = rsqrtf(n2);
        *(float4*)&g_ys[((size_t)b * NN + n) * CC + g * 4] =
            make_float4(v[0]*r, v[1]*r, v[2]*r, v[3]*r);
    }
}

// ---------------------------------------------------------------------------
// sphere_x0: x0 = sphere(x) (fp32) + fp16 hi/lo. One thread per 4-group.
// ---------------------------------------------------------------------------
__global__ __launch_bounds__(256) void sphere_x0(const float* __restrict__ x)
{
    const int idx = blockIdx.x * 256 + threadIdx.x;   // group index
    float4 v = ((const float4*)x)[idx];
    float n2 = fmaxf(v.x*v.x + v.y*v.y + v.z*v.z + v.w*v.w, EPS_SPHERE);
    float rs = rsqrtf(n2);
    float o0 = v.x*rs, o1 = v.y*rs, o2 = v.z*rs, o3 = v.w*rs;
    ((float4*)g_x0)[idx] = make_float4(o0, o1, o2, o3);
    __half h0 = __float2half_rn(o0), h1 = __float2half_rn(o1);
    __half h2 = __float2half_rn(o2), h3 = __float2half_rn(o3);
    __half2 hh0 = __halves2half2(h0, h1), hh1 = __halves2half2(h2, h3);
    ((__half2*)g_xh)[idx * 2]     = hh0;
    ((__half2*)g_xh)[idx * 2 + 1] = hh1;
    __half2 ll0 = __halves2half2(__float2half_rn(o0 - __half2float(h0)),
                                 __float2half_rn(o1 - __half2float(h1)));
    __half2 ll1 = __halves2half2(__float2half_rn(o2 - __half2float(h2)),
                                 __float2half_rn(o3 - __half2float(h3)));
    ((__half2*)g_xl)[idx * 2]     = ll0;
    ((__half2*)g_xl)[idx * 2 + 1] = ll1;
}

// ---------------------------------------------------------------------------
// step_mma: one Kuramoto step. CTA tile: M=128 x N=256(full C), K=2048, BK=64.
// fp16 split GEMM via mma.sync (hi*hi + lo*hi + hi*lo), fp32 acc, fused epilogue.
// ---------------------------------------------------------------------------
#define BK 64
#define OFF_AHI 0
#define OFF_ALO 16384
#define OFF_BHI 32768
#define OFF_BLO 65536
#define STAGE   98304
#define SMEM_TOTAL (2 * STAGE)      // 196608
#define CS_STRIDE 264               // fp32 epilogue staging stride

__global__ __launch_bounds__(256, 1) void step_mma(const float* __restrict__ xc_in,
                                                   float* __restrict__ xout,
                                                   const float* __restrict__ omega,
                                                   const float* __restrict__ gammap)
{
    extern __shared__ __align__(16) char dsm[];
    const uint32_t smem = smem_u32(dsm);
    const int tid  = threadIdx.x;
    const int lane = tid & 31;
    const int wid  = tid >> 5;
    const int wm   = wid & 1;       // warp row (0..1) -> 64 rows each
    const int wn   = wid >> 1;      // warp col (0..3) -> 64 cols each
    const int b    = blockIdx.y;
    const int row0 = blockIdx.x * 128;

    const __half* __restrict__ Ah = g_Khi + (size_t)b * NN * NN + (size_t)row0 * NN;
    const __half* __restrict__ Al = g_Klo + (size_t)b * NN * NN + (size_t)row0 * NN;
    const __half* __restrict__ Bh = g_xh + (size_t)b * NN * CC;
    const __half* __restrict__ Bl = g_xl + (size_t)b * NN * CC;

    float acc[4][8][4];
#pragma unroll
    for (int i = 0; i < 4; i++)
#pragma unroll
        for (int j = 0; j < 8; j++)
#pragma unroll
            for (int k = 0; k < 4; k++) acc[i][j][k] = 0.f;

    auto load_stage = [&](int chunk, int buf) {
        const uint32_t sb = smem + buf * STAGE;
        const int k0 = chunk * BK;
#pragma unroll
        for (int it = 0; it < 4; it++) {                 // A: 128 rows x 8 chunks
            int idx = tid + it * 256;
            int m = idx >> 3, ck = idx & 7;
            uint32_t off = m * 128 + ((ck ^ (m & 7)) << 4);
            const size_t go = (size_t)m * NN + k0 + ck * 8;
            cp16(sb + OFF_AHI + off, Ah + go);
            cp16(sb + OFF_ALO + off, Al + go);
        }
#pragma unroll
        for (int it = 0; it < 8; it++) {                 // B: 64 k-rows x 32 chunks
            int idx = tid + it * 256;
            int kr = idx >> 5, nc = idx & 31;
            uint32_t off = kr * 512 + ((nc ^ (kr & 7)) << 4);
            const size_t go = (size_t)(k0 + kr) * CC + nc * 8;
            cp16(sb + OFF_BHI + off, Bh + go);
            cp16(sb + OFF_BLO + off, Bl + go);
        }
        CP_COMMIT();
    };

    load_stage(0, 0);

#pragma unroll 1
    for (int i = 0; i < 32; i++) {
        const int buf = i & 1;
        if (i < 31) { load_stage(i + 1, buf ^ 1); CP_WAIT(1); }
        else        { CP_WAIT(0); }
        __syncthreads();

        const uint32_t sA  = smem + buf * STAGE + OFF_AHI;
        const uint32_t sAl = smem + buf * STAGE + OFF_ALO;
        const uint32_t sB  = smem + buf * STAGE + OFF_BHI;
        const uint32_t sBl = smem + buf * STAGE + OFF_BLO;

#pragma unroll
        for (int kk = 0; kk < 4; kk++) {
            uint32_t ah[4][4], al[4][4];
#pragma unroll
            for (int mf = 0; mf < 4; mf++) {
                const int m = wm * 64 + mf * 16 + (lane & 15);
                const int kc = kk * 2 + (lane >> 4);
                const uint32_t off = m * 128 + ((kc ^ (m & 7)) << 4);
                LDSM_X4(ah[mf][0], ah[mf][1], ah[mf][2], ah[mf][3], sA + off);
                LDSM_X4(al[mf][0], al[mf][1], al[mf][2], al[mf][3], sAl + off);
            }
#pragma unroll
            for (int nf2 = 0; nf2 < 4; nf2++) {
                const int kr = kk * 16 + (lane & 15);
                const int nc = wn * 8 + nf2 * 2 + (lane >> 4);
                const uint32_t off = kr * 512 + ((nc ^ (kr & 7)) << 4);
                uint32_t bh[4], bl[4];
                LDSM_X4T(bh[0], bh[1], bh[2], bh[3], sB + off);
                LDSM_X4T(bl[0], bl[1], bl[2], bl[3], sBl + off);
#pragma unroll
                for (int mf = 0; mf < 4; mf++) {
#pragma unroll
                    for (int j = 0; j < 2; j++) {
                        float* d = acc[mf][nf2 * 2 + j];
                        MMA16816(d, ah[mf][0], ah[mf][1], ah[mf][2], ah[mf][3],
                                 bh[j * 2], bh[j * 2 + 1]);
                        MMA16816(d, al[mf][0], al[mf][1], al[mf][2], al[mf][3],
                                 bh[j * 2], bh[j * 2 + 1]);
                        MMA16816(d, ah[mf][0], ah[mf][1], ah[mf][2], ah[mf][3],
                                 bl[j * 2], bl[j * 2 + 1]);
                    }
                }
            }
        }
        __syncthreads();
    }

    // ----- stage acc through smem (reuse stage buffers) -----
    float* cs = (float*)dsm;
#pragma unroll
    for (int mf = 0; mf < 4; mf++)
#pragma unroll
        for (int mh = 0; mh < 2; mh++)
#pragma unroll
            for (int nf = 0; nf < 8; nf++) {
                const int row = wm * 64 + mf * 16 + mh * 8 + (lane >> 2);
                const int col = wn * 64 + nf * 8 + (lane & 3) * 2;
                *(float2*)&cs[row * CS_STRIDE + col] =
                    make_float2(acc[mf][nf][mh * 2], acc[mf][nf][mh * 2 + 1]);
            }
    __syncthreads();

    // ----- fused epilogue: warp w handles rows w*16 .. w*16+15, lane = 8 cols -----
    const float gamma = *gammap;
    const int c = lane * 8;
    const float og0 = fabsf(omega[(c >> 1) + 0]);
    const float og1 = fabsf(omega[(c >> 1) + 1]);
    const float og2 = fabsf(omega[(c >> 1) + 2]);
    const float og3 = fabsf(omega[(c >> 1) + 3]);
    const float* __restrict__ Xg = (xc_in ? xc_in : g_x0) + (size_t)b * NN * CC;
    const float* __restrict__ Yg = g_ys + (size_t)b * NN * CC;
    float* __restrict__ Og = xout + (size_t)b * NN * CC;
    __half* __restrict__ XHg = g_xh + (size_t)b * NN * CC;
    __half* __restrict__ XLg = g_xl + (size_t)b * NN * CC;

#pragma unroll 1
    for (int rr = 0; rr < 16; rr++) {
        const int lr = wid * 16 + rr;            // local row 0..127
        const size_t goff = (size_t)(row0 + lr) * CC + c;
        float4 k0 = *(const float4*)&cs[lr * CS_STRIDE + c];
        float4 k1 = *(const float4*)&cs[lr * CS_STRIDE + c + 4];
        float4 x0 = *(const float4*)&Xg[goff];
        float4 x1 = *(const float4*)&Xg[goff + 4];
        float4 y0 = *(const float4*)&Yg[goff];
        float4 y1 = *(const float4*)&Yg[goff + 4];

        float ox[8];
        {   // group 0 (c..c+3)
            float f0 = k0.x + y0.x, f1 = k0.y + y0.y, f2 = k0.z + y0.z, f3 = k0.w + y0.w;
            float sim = x0.x*f0 + x0.y*f1 + x0.z*f2 + x0.w*f3;
            float d0 =  og0 * x0.y + (f0 - sim * x0.x);
            float d1 = -og0 * x0.x + (f1 - sim * x0.y);
            float d2 =  og1 * x0.w + (f2 - sim * x0.z);
            float d3 = -og1 * x0.z + (f3 - sim * x0.w);
            float u0 = x0.x + gamma * d0, u1 = x0.y + gamma * d1;
            float u2 = x0.z + gamma * d2, u3 = x0.w + gamma * d3;
            float rs = rsqrtf(fmaxf(u0*u0 + u1*u1 + u2*u2 + u3*u3, EPS_SPHERE));
            ox[0] = u0*rs; ox[1] = u1*rs; ox[2] = u2*rs; ox[3] = u3*rs;
        }
        {   // group 1 (c+4..c+7)
            float f0 = k1.x + y1.x, f1 = k1.y + y1.y, f2 = k1.z + y1.z, f3 = k1.w + y1.w;
            float sim = x1.x*f0 + x1.y*f1 + x1.z*f2 + x1.w*f3;
            float d0 =  og2 * x1.y + (f0 - sim * x1.x);
            float d1 = -og2 * x1.x + (f1 - sim * x1.y);
            float d2 =  og3 * x1.w + (f2 - sim * x1.z);
            float d3 = -og3 * x1.z + (f3 - sim * x1.w);
            float u0 = x1.x + gamma * d0, u1 = x1.y + gamma * d1;
            float u2 = x1.z + gamma * d2, u3 = x1.w + gamma * d3;
            float rs = rsqrtf(fmaxf(u0*u0 + u1*u1 + u2*u2 + u3*u3, EPS_SPHERE));
            ox[4] = u0*rs; ox[5] = u1*rs; ox[6] = u2*rs; ox[7] = u3*rs;
        }
        *(float4*)&Og[goff]     = make_float4(ox[0], ox[1], ox[2], ox[3]);
        *(float4*)&Og[goff + 4] = make_float4(ox[4], ox[5], ox[6], ox[7]);

        __half h[8]; uint32_t hw[4], lw[4];
#pragma unroll
        for (int j = 0; j < 8; j++) h[j] = __float2half_rn(ox[j]);
#pragma unroll
        for (int j = 0; j < 4; j++) {
            __half2 p = __halves2half2(h[2*j], h[2*j+1]);
            hw[j] = *(uint32_t*)&p;
            __half2 q = __halves2half2(__float2half_rn(ox[2*j]   - __half2float(h[2*j])),
                                       __float2half_rn(ox[2*j+1] - __half2float(h[2*j+1])));
            lw[j] = *(uint32_t*)&q;
        }
        *(uint4*)&XHg[goff] = make_uint4(hw[0], hw[1], hw[2], hw[3]);
        *(uint4*)&XLg[goff] = make_uint4(lw[0], lw[1], lw[2], lw[3]);
    }
}

// ---------------------------------------------------------------------------
// Launch. Inputs: x, y, sc, U, omega_param, gn_w, gn_b, gamma, Q.
// Output: xs [Q=8, B, N, C] fp32.
// ---------------------------------------------------------------------------
extern "C" void kernel_launch(void* const* d_in, const int* in_sizes, int n_in,
                              void* d_out, int out_size)
{
    const float* x     = (const float*)d_in[0];
    const float* y     = (const float*)d_in[1];
    const float* sc    = (const float*)d_in[2];
    const float* U     = (const float*)d_in[3];
    const float* omega = (const float*)d_in[4];
    const float* gw    = (const float*)d_in[5];
    const float* gb    = (const float*)d_in[6];
    const float* gamma = (const float*)d_in[7];
    float* out = (float*)d_out;

    static int attr_set = 0;
    if (!attr_set) {
        cudaFuncSetAttribute(step_mma, cudaFuncAttributeMaxDynamicSharedMemorySize,
                             SMEM_TOTAL);
        attr_set = 1;
    }

    prep_K<<<dim3(NN / 32, NN / 32), dim3(32, 32)>>>(sc, U);
    gn_sphere<<<BATCH * 64, 256>>>(y, gw, gb);
    sphere_x0<<<(BATCH * NN * CC / 4) / 256, 256>>>(x);

    const size_t step_elems = (size_t)BATCH * NN * CC;
    for (int q = 0; q < QSTEPS; q++) {
        const float* xc = (q == 0) ? nullptr : out + (size_t)(q - 1) * step_elems;
        step_mma<<<dim3(16, BATCH), 256, SMEM_TOTAL>>>(xc, out + (size_t)q * step_elems,
                                                       omega, gamma);
    }
}

// round 4
// speedup vs baseline: 3.3931x; 1.0299x over previous
#include <cuda_runtime.h>
#include <cuda_fp16.h>
#include <cstdint>
#include <math.h>

#define BATCH 8
#define NN    2048
#define CC    256
#define RANK  16
#define QSTEPS 8
#define EPS_SPHERE 1e-6f
#define EPS_GN     1e-5f

// ---------------- device scratch (no allocation allowed) ----------------
__device__ __half g_Khi[(size_t)BATCH * NN * NN];   // 67 MB
__device__ __half g_Klo[(size_t)BATCH * NN * NN];   // 67 MB
__device__ __half g_xh [(size_t)BATCH * NN * CC];   // x (fp16 hi), [B,N,C]
__device__ __half g_xl [(size_t)BATCH * NN * CC];   // x (fp16 lo), [B,N,C]
__device__ float  g_ys [(size_t)BATCH * NN * CC];
__device__ float  g_x0 [(size_t)BATCH * NN * CC];

// ---------------- helpers ----------------
__device__ __forceinline__ uint32_t smem_u32(const void* p) {
    uint32_t a;
    asm("{ .reg .u64 t; cvta.to.shared.u64 t, %1; cvt.u32.u64 %0, t; }" : "=r"(a) : "l"(p));
    return a;
}
__device__ __forceinline__ void cp16(uint32_t dst, const void* src) {
    asm volatile("cp.async.cg.shared.global [%0], [%1], 16;" :: "r"(dst), "l"(src));
}
#define CP_COMMIT() asm volatile("cp.async.commit_group;" ::: "memory")
#define CP_WAIT(n)  asm volatile("cp.async.wait_group %0;" :: "n"(n) : "memory")

#define LDSM_X4(r0,r1,r2,r3, a) \
    asm volatile("ldmatrix.sync.aligned.m8n8.x4.shared.b16 {%0,%1,%2,%3}, [%4];" \
        : "=r"(r0), "=r"(r1), "=r"(r2), "=r"(r3) : "r"(a))
#define LDSM_X4T(r0,r1,r2,r3, a) \
    asm volatile("ldmatrix.sync.aligned.m8n8.x4.trans.shared.b16 {%0,%1,%2,%3}, [%4];" \
        : "=r"(r0), "=r"(r1), "=r"(r2), "=r"(r3) : "r"(a))

#define MMA16816(d, a0,a1,a2,a3, b0,b1) \
    asm volatile("mma.sync.aligned.m16n8k16.row.col.f32.f16.f16.f32 " \
        "{%0,%1,%2,%3}, {%4,%5,%6,%7}, {%8,%9}, {%0,%1,%2,%3};" \
        : "+f"((d)[0]), "+f"((d)[1]), "+f"((d)[2]), "+f"((d)[3]) \
        : "r"(a0), "r"(a1), "r"(a2), "r"(a3), "r"(b0), "r"(b1))

// ---------------------------------------------------------------------------
// prep_K: K[b,n,m] = 0.5*(sc[b,n,m]+sc[b,m,n]) * sigmoid(U[n]·U[m]); symmetric,
// each block (m0 >= n0) writes both triangles, split into fp16 hi/lo.
// ---------------------------------------------------------------------------
__global__ __launch_bounds__(1024) void prep_K(const float* __restrict__ sc,
                                               const float* __restrict__ U)
{
    const int n0 = blockIdx.y * 32, m0 = blockIdx.x * 32;
    if (m0 < n0) return;

    __shared__ float Un[32][17];
    __shared__ float Um[32][17];
    __shared__ float tT[32][33];
    __shared__ float vS[32][33];

    const int tx = threadIdx.x, ty = threadIdx.y;
    const int t = ty * 32 + tx;

    if (t < 512)      Un[t >> 4][t & 15] = U[(n0 + (t >> 4)) * RANK + (t & 15)];
    else { int u = t - 512; Um[u >> 4][u & 15] = U[(m0 + (u >> 4)) * RANK + (u & 15)]; }
    __syncthreads();

    float d = 0.f;
#pragma unroll
    for (int k = 0; k < RANK; k++) d += Un[ty][k] * Um[tx][k];
    const float a = 1.f / (1.f + __expf(-d));

    const int n = n0 + ty, m = m0 + tx;
#pragma unroll 1
    for (int b = 0; b < BATCH; b++) {
        const size_t base = (size_t)b * NN * NN;
        tT[ty][tx] = sc[base + (size_t)(m0 + ty) * NN + (n0 + tx)];
        __syncthreads();
        const float v = 0.5f * (sc[base + (size_t)n * NN + m] + tT[tx][ty]) * a;
        __half hi = __float2half_rn(v);
        __half lo = __float2half_rn(v - __half2float(hi));
        const size_t o1 = base + (size_t)n * NN + m;
        g_Khi[o1] = hi; g_Klo[o1] = lo;
        vS[ty][tx] = v;
        __syncthreads();
        if (m0 != n0) {
            const float vt = vS[tx][ty];
            __half hi2 = __float2half_rn(vt);
            __half lo2 = __float2half_rn(vt - __half2float(hi2));
            const size_t o2 = base + (size_t)(m0 + ty) * NN + (n0 + tx);
            g_Khi[o2] = hi2; g_Klo[o2] = lo2;
        }
        __syncthreads();
    }
}

// ---------------------------------------------------------------------------
// gn_sphere: GroupNorm over (4ch x 2048) per (b,g) then transpose + sphere.
// ---------------------------------------------------------------------------
__global__ __launch_bounds__(256) void gn_sphere(const float* __restrict__ y,
                                                 const float* __restrict__ gw,
                                                 const float* __restrict__ gb)
{
    const int b = blockIdx.x >> 6;
    const int g = blockIdx.x & 63;
    const float* yg = y + ((size_t)b * CC + g * 4) * NN;
    const int tid = threadIdx.x;

    float s = 0.f, s2 = 0.f;
    for (int i = tid; i < 4 * NN; i += 256) { float v = yg[i]; s += v; s2 += v * v; }
    __shared__ float shs[8], shs2[8];
#pragma unroll
    for (int o = 16; o; o >>= 1) {
        s  += __shfl_down_sync(0xffffffffu, s,  o);
        s2 += __shfl_down_sync(0xffffffffu, s2, o);
    }
    if ((tid & 31) == 0) { shs[tid >> 5] = s; shs2[tid >> 5] = s2; }
    __syncthreads();
    if (tid == 0) {
        float ts = 0.f, ts2 = 0.f;
#pragma unroll
        for (int i = 0; i < 8; i++) { ts += shs[i]; ts2 += shs2[i]; }
        shs[0] = ts; shs2[0] = ts2;
    }
    __syncthreads();
    const float mu   = shs[0] * (1.f / (4 * NN));
    const float var  = shs2[0] * (1.f / (4 * NN)) - mu * mu;
    const float rstd = rsqrtf(var + EPS_GN);

    float w[4], bb[4];
#pragma unroll
    for (int j = 0; j < 4; j++) { w[j] = gw[g * 4 + j]; bb[j] = gb[g * 4 + j]; }

    for (int n = tid; n < NN; n += 256) {
        float v[4];
#pragma unroll
        for (int j = 0; j < 4; j++)
            v[j] = (yg[j * NN + n] - mu) * rstd * w[j] + bb[j];
        float n2 = fmaxf(v[0]*v[0] + v[1]*v[1] + v[2]*v[2] + v[3]*v[3], EPS_SPHERE);
        float r = rsqrtf(n2);
        *(float4*)&g_ys[((size_t)b * NN + n) * CC + g * 4] =
            make_float4(v[0]*r, v[1]*r, v[2]*r, v[3]*r);
    }
}

// ---------------------------------------------------------------------------
// sphere_x0: x0 = sphere(x) (fp32) + fp16 hi/lo. One thread per 4-group.
// ---------------------------------------------------------------------------
__global__ __launch_bounds__(256) void sphere_x0(const float* __restrict__ x)
{
    const int idx = blockIdx.x * 256 + threadIdx.x;   // group index
    float4 v = ((const float4*)x)[idx];
    float n2 = fmaxf(v.x*v.x + v.y*v.y + v.z*v.z + v.w*v.w, EPS_SPHERE);
    float rs = rsqrtf(n2);
    float o0 = v.x*rs, o1 = v.y*rs, o2 = v.z*rs, o3 = v.w*rs;
    ((float4*)g_x0)[idx] = make_float4(o0, o1, o2, o3);
    __half h0 = __float2half_rn(o0), h1 = __float2half_rn(o1);
    __half h2 = __float2half_rn(o2), h3 = __float2half_rn(o3);
    __half2 hh0 = __halves2half2(h0, h1), hh1 = __halves2half2(h2, h3);
    ((__half2*)g_xh)[idx * 2]     = hh0;
    ((__half2*)g_xh)[idx * 2 + 1] = hh1;
    __half2 ll0 = __halves2half2(__float2half_rn(o0 - __half2float(h0)),
                                 __float2half_rn(o1 - __half2float(h1)));
    __half2 ll1 = __halves2half2(__float2half_rn(o2 - __half2float(h2)),
                                 __float2half_rn(o3 - __half2float(h3)));
    ((__half2*)g_xl)[idx * 2]     = ll0;
    ((__half2*)g_xl)[idx * 2 + 1] = ll1;
}

// ---------------------------------------------------------------------------
// step_mma: one Kuramoto step. CTA: M=128 x N=256(full C), K=2048, BK=64.
// 512 threads, 16 warps, warp tile 64x32. fp16 split GEMM (hi*hi+lo*hi+hi*lo).
// ---------------------------------------------------------------------------
#define BK 64
#define OFF_AHI 0
#define OFF_ALO 16384
#define OFF_BHI 32768
#define OFF_BLO 65536
#define STAGE   98304
#define SMEM_TOTAL (2 * STAGE)      // 196608
#define CS_STRIDE 264               // fp32 epilogue staging stride

__global__ __launch_bounds__(512, 1) void step_mma(const float* __restrict__ xc_in,
                                                   float* __restrict__ xout,
                                                   const float* __restrict__ omega,
                                                   const float* __restrict__ gammap)
{
    extern __shared__ __align__(16) char dsm[];
    const uint32_t smem = smem_u32(dsm);
    const int tid  = threadIdx.x;
    const int lane = tid & 31;
    const int wid  = tid >> 5;
    const int wm   = wid & 1;       // warp row (0..1) -> 64 rows each
    const int wn   = wid >> 1;      // warp col (0..7) -> 32 cols each
    const int b    = blockIdx.y;
    const int row0 = blockIdx.x * 128;

    const __half* __restrict__ Ah = g_Khi + (size_t)b * NN * NN + (size_t)row0 * NN;
    const __half* __restrict__ Al = g_Klo + (size_t)b * NN * NN + (size_t)row0 * NN;
    const __half* __restrict__ Bh = g_xh + (size_t)b * NN * CC;
    const __half* __restrict__ Bl = g_xl + (size_t)b * NN * CC;

    float acc[4][4][4];             // [mf 16-row][nf 8-col][frag]
#pragma unroll
    for (int i = 0; i < 4; i++)
#pragma unroll
        for (int j = 0; j < 4; j++)
#pragma unroll
            for (int k = 0; k < 4; k++) acc[i][j][k] = 0.f;

    auto load_stage = [&](int chunk, int buf) {
        const uint32_t sb = smem + buf * STAGE;
        const int k0 = chunk * BK;
#pragma unroll
        for (int it = 0; it < 2; it++) {                 // A: 128 rows x 8 chunks
            int idx = tid + it * 512;
            int m = idx >> 3, ck = idx & 7;
            uint32_t off = m * 128 + ((ck ^ (m & 7)) << 4);
            const size_t go = (size_t)m * NN + k0 + ck * 8;
            cp16(sb + OFF_AHI + off, Ah + go);
            cp16(sb + OFF_ALO + off, Al + go);
        }
#pragma unroll
        for (int it = 0; it < 4; it++) {                 // B: 64 k-rows x 32 chunks
            int idx = tid + it * 512;
            int kr = idx >> 5, nc = idx & 31;
            uint32_t off = kr * 512 + ((nc ^ (kr & 7)) << 4);
            const size_t go = (size_t)(k0 + kr) * CC + nc * 8;
            cp16(sb + OFF_BHI + off, Bh + go);
            cp16(sb + OFF_BLO + off, Bl + go);
        }
        CP_COMMIT();
    };

    load_stage(0, 0);

#pragma unroll 1
    for (int i = 0; i < 32; i++) {
        const int buf = i & 1;
        if (i < 31) { load_stage(i + 1, buf ^ 1); CP_WAIT(1); }
        else        { CP_WAIT(0); }
        __syncthreads();

        const uint32_t sA  = smem + buf * STAGE + OFF_AHI;
        const uint32_t sAl = smem + buf * STAGE + OFF_ALO;
        const uint32_t sB  = smem + buf * STAGE + OFF_BHI;
        const uint32_t sBl = smem + buf * STAGE + OFF_BLO;

#pragma unroll
        for (int kk = 0; kk < 4; kk++) {
            // B fragments for this warp's 32 columns, k16 slice kk
            uint32_t bh[2][4], bl[2][4];
#pragma unroll
            for (int nf2 = 0; nf2 < 2; nf2++) {
                const int kr = kk * 16 + (lane & 15);
                const int nc = wn * 4 + nf2 * 2 + (lane >> 4);
                const uint32_t off = kr * 512 + ((nc ^ (kr & 7)) << 4);
                LDSM_X4T(bh[nf2][0], bh[nf2][1], bh[nf2][2], bh[nf2][3], sB  + off);
                LDSM_X4T(bl[nf2][0], bl[nf2][1], bl[nf2][2], bl[nf2][3], sBl + off);
            }
#pragma unroll
            for (int mf = 0; mf < 4; mf++) {
                const int m = wm * 64 + mf * 16 + (lane & 15);
                const int kc = kk * 2 + (lane >> 4);
                const uint32_t off = m * 128 + ((kc ^ (m & 7)) << 4);
                uint32_t ah0, ah1, ah2, ah3, al0, al1, al2, al3;
                LDSM_X4(ah0, ah1, ah2, ah3, sA  + off);
                LDSM_X4(al0, al1, al2, al3, sAl + off);
#pragma unroll
                for (int nf2 = 0; nf2 < 2; nf2++) {
#pragma unroll
                    for (int j = 0; j < 2; j++) {
                        float* d = acc[mf][nf2 * 2 + j];
                        MMA16816(d, ah0, ah1, ah2, ah3, bh[nf2][j*2], bh[nf2][j*2+1]);
                        MMA16816(d, al0, al1, al2, al3, bh[nf2][j*2], bh[nf2][j*2+1]);
                        MMA16816(d, ah0, ah1, ah2, ah3, bl[nf2][j*2], bl[nf2][j*2+1]);
                    }
                }
            }
        }
        __syncthreads();
    }

    // ----- stage acc through smem (reuse stage buffers) -----
    float* cs = (float*)dsm;
#pragma unroll
    for (int mf = 0; mf < 4; mf++)
#pragma unroll
        for (int mh = 0; mh < 2; mh++)
#pragma unroll
            for (int nf = 0; nf < 4; nf++) {
                const int row = wm * 64 + mf * 16 + mh * 8 + (lane >> 2);
                const int col = wn * 32 + nf * 8 + (lane & 3) * 2;
                *(float2*)&cs[row * CS_STRIDE + col] =
                    make_float2(acc[mf][nf][mh * 2], acc[mf][nf][mh * 2 + 1]);
            }
    __syncthreads();

    // ----- fused epilogue: warp w -> rows w*8 .. w*8+7, lane -> 8 cols -----
    const float gamma = *gammap;
    const int c = lane * 8;
    const float og0 = fabsf(omega[(c >> 1) + 0]);
    const float og1 = fabsf(omega[(c >> 1) + 1]);
    const float og2 = fabsf(omega[(c >> 1) + 2]);
    const float og3 = fabsf(omega[(c >> 1) + 3]);
    const float* __restrict__ Xg = (xc_in ? xc_in : g_x0) + (size_t)b * NN * CC;
    const float* __restrict__ Yg = g_ys + (size_t)b * NN * CC;
    float* __restrict__ Og = xout + (size_t)b * NN * CC;
    __half* __restrict__ XHg = g_xh + (size_t)b * NN * CC;
    __half* __restrict__ XLg = g_xl + (size_t)b * NN * CC;

#pragma unroll 1
    for (int rr = 0; rr < 8; rr++) {
        const int lr = wid * 8 + rr;             // local row 0..127
        const size_t goff = (size_t)(row0 + lr) * CC + c;
        float4 k0 = *(const float4*)&cs[lr * CS_STRIDE + c];
        float4 k1 = *(const float4*)&cs[lr * CS_STRIDE + c + 4];
        float4 x0 = *(const float4*)&Xg[goff];
        float4 x1 = *(const float4*)&Xg[goff + 4];
        float4 y0 = *(const float4*)&Yg[goff];
        float4 y1 = *(const float4*)&Yg[goff + 4];

        float ox[8];
        {
            float f0 = k0.x + y0.x, f1 = k0.y + y0.y, f2 = k0.z + y0.z, f3 = k0.w + y0.w;
            float sim = x0.x*f0 + x0.y*f1 + x0.z*f2 + x0.w*f3;
            float d0 =  og0 * x0.y + (f0 - sim * x0.x);
            float d1 = -og0 * x0.x + (f1 - sim * x0.y);
            float d2 =  og1 * x0.w + (f2 - sim * x0.z);
            float d3 = -og1 * x0.z + (f3 - sim * x0.w);
            float u0 = x0.x + gamma * d0, u1 = x0.y + gamma * d1;
            float u2 = x0.z + gamma * d2, u3 = x0.w + gamma * d3;
            float rs = rsqrtf(fmaxf(u0*u0 + u1*u1 + u2*u2 + u3*u3, EPS_SPHERE));
            ox[0] = u0*rs; ox[1] = u1*rs; ox[2] = u2*rs; ox[3] = u3*rs;
        }
        {
            float f0 = k1.x + y1.x, f1 = k1.y + y1.y, f2 = k1.z + y1.z, f3 = k1.w + y1.w;
            float sim = x1.x*f0 + x1.y*f1 + x1.z*f2 + x1.w*f3;
            float d0 =  og2 * x1.y + (f0 - sim * x1.x);
            float d1 = -og2 * x1.x + (f1 - sim * x1.y);
            float d2 =  og3 * x1.w + (f2 - sim * x1.z);
            float d3 = -og3 * x1.z + (f3 - sim * x1.w);
            float u0 = x1.x + gamma * d0, u1 = x1.y + gamma * d1;
            float u2 = x1.z + gamma * d2, u3 = x1.w + gamma * d3;
            float rs = rsqrtf(fmaxf(u0*u0 + u1*u1 + u2*u2 + u3*u3, EPS_SPHERE));
            ox[4] = u0*rs; ox[5] = u1*rs; ox[6] = u2*rs; ox[7] = u3*rs;
        }
        *(float4*)&Og[goff]     = make_float4(ox[0], ox[1], ox[2], ox[3]);
        *(float4*)&Og[goff + 4] = make_float4(ox[4], ox[5], ox[6], ox[7]);

        __half h[8]; uint32_t hw[4], lw[4];
#pragma unroll
        for (int j = 0; j < 8; j++) h[j] = __float2half_rn(ox[j]);
#pragma unroll
        for (int j = 0; j < 4; j++) {
            __half2 p = __halves2half2(h[2*j], h[2*j+1]);
            hw[j] = *(uint32_t*)&p;
            __half2 q = __halves2half2(__float2half_rn(ox[2*j]   - __half2float(h[2*j])),
                                       __float2half_rn(ox[2*j+1] - __half2float(h[2*j+1])));
            lw[j] = *(uint32_t*)&q;
        }
        *(uint4*)&XHg[goff] = make_uint4(hw[0], hw[1], hw[2], hw[3]);
        *(uint4*)&XLg[goff] = make_uint4(lw[0], lw[1], lw[2], lw[3]);
    }
}

// ---------------------------------------------------------------------------
// Launch. Inputs: x, y, sc, U, omega_param, gn_w, gn_b, gamma, Q.
// Output: xs [Q=8, B, N, C] fp32.
// ---------------------------------------------------------------------------
extern "C" void kernel_launch(void* const* d_in, const int* in_sizes, int n_in,
                              void* d_out, int out_size)
{
    const float* x     = (const float*)d_in[0];
    const float* y     = (const float*)d_in[1];
    const float* sc    = (const float*)d_in[2];
    const float* U     = (const float*)d_in[3];
    const float* omega = (const float*)d_in[4];
    const float* gw    = (const float*)d_in[5];
    const float* gb    = (const float*)d_in[6];
    const float* gamma = (const float*)d_in[7];
    float* out = (float*)d_out;

    static int attr_set = 0;
    if (!attr_set) {
        cudaFuncSetAttribute(step_mma, cudaFuncAttributeMaxDynamicSharedMemorySize,
                             SMEM_TOTAL);
        attr_set = 1;
    }

    prep_K<<<dim3(NN / 32, NN / 32), dim3(32, 32)>>>(sc, U);
    gn_sphere<<<BATCH * 64, 256>>>(y, gw, gb);
    sphere_x0<<<(BATCH * NN * CC / 4) / 256, 256>>>(x);

    const size_t step_elems = (size_t)BATCH * NN * CC;
    for (int q = 0; q < QSTEPS; q++) {
        const float* xc = (q == 0) ? nullptr : out + (size_t)(q - 1) * step_elems;
        step_mma<<<dim3(16, BATCH), 512, SMEM_TOTAL>>>(xc, out + (size_t)q * step_elems,
                                                       omega, gamma);
    }
}

// round 5
// speedup vs baseline: 4.6017x; 1.3562x over previous
#include <cuda_runtime.h>
#include <cuda_fp16.h>
#include <cstdint>
#include <math.h>

#define BATCH 8
#define NN    2048
#define CC    256
#define RANK  16
#define QSTEPS 8
#define EPS_SPHERE 1e-6f
#define EPS_GN     1e-5f

// ---------------- device scratch (no allocation allowed) ----------------
__device__ __half g_Khi[(size_t)BATCH * NN * NN];   // 67 MB
__device__ __half g_Klo[(size_t)BATCH * NN * NN];   // 67 MB
__device__ __half g_xh [(size_t)BATCH * NN * CC];   // x (fp16), [B,N,C]
__device__ float  g_ys [(size_t)BATCH * NN * CC];
__device__ float  g_x0 [(size_t)BATCH * NN * CC];

// ---------------- helpers ----------------
__device__ __forceinline__ uint32_t smem_u32(const void* p) {
    uint32_t a;
    asm("{ .reg .u64 t; cvta.to.shared.u64 t, %1; cvt.u32.u64 %0, t; }" : "=r"(a) : "l"(p));
    return a;
}
__device__ __forceinline__ void cp16(uint32_t dst, const void* src) {
    asm volatile("cp.async.cg.shared.global [%0], [%1], 16;" :: "r"(dst), "l"(src));
}
#define CP_COMMIT() asm volatile("cp.async.commit_group;" ::: "memory")
#define CP_WAIT(n)  asm volatile("cp.async.wait_group %0;" :: "n"(n) : "memory")

#define LDSM_X4(r0,r1,r2,r3, a) \
    asm volatile("ldmatrix.sync.aligned.m8n8.x4.shared.b16 {%0,%1,%2,%3}, [%4];" \
        : "=r"(r0), "=r"(r1), "=r"(r2), "=r"(r3) : "r"(a))
#define LDSM_X4T(r0,r1,r2,r3, a) \
    asm volatile("ldmatrix.sync.aligned.m8n8.x4.trans.shared.b16 {%0,%1,%2,%3}, [%4];" \
        : "=r"(r0), "=r"(r1), "=r"(r2), "=r"(r3) : "r"(a))

#define MMA16816(d, a0,a1,a2,a3, b0,b1) \
    asm volatile("mma.sync.aligned.m16n8k16.row.col.f32.f16.f16.f32 " \
        "{%0,%1,%2,%3}, {%4,%5,%6,%7}, {%8,%9}, {%0,%1,%2,%3};" \
        : "+f"((d)[0]), "+f"((d)[1]), "+f"((d)[2]), "+f"((d)[3]) \
        : "r"(a0), "r"(a1), "r"(a2), "r"(a3), "r"(b0), "r"(b1))

// ---------------------------------------------------------------------------
// prep_K: K[b,n,m] = 0.5*(sc[b,n,m]+sc[b,m,n]) * sigmoid(U[n]·U[m]); symmetric,
// each block (m0 >= n0) writes both triangles, split into fp16 hi/lo.
// ---------------------------------------------------------------------------
__global__ __launch_bounds__(1024) void prep_K(const float* __restrict__ sc,
                                               const float* __restrict__ U)
{
    const int n0 = blockIdx.y * 32, m0 = blockIdx.x * 32;
    if (m0 < n0) return;

    __shared__ float Un[32][17];
    __shared__ float Um[32][17];
    __shared__ float tT[32][33];
    __shared__ float vS[32][33];

    const int tx = threadIdx.x, ty = threadIdx.y;
    const int t = ty * 32 + tx;

    if (t < 512)      Un[t >> 4][t & 15] = U[(n0 + (t >> 4)) * RANK + (t & 15)];
    else { int u = t - 512; Um[u >> 4][u & 15] = U[(m0 + (u >> 4)) * RANK + (u & 15)]; }
    __syncthreads();

    float d = 0.f;
#pragma unroll
    for (int k = 0; k < RANK; k++) d += Un[ty][k] * Um[tx][k];
    const float a = 1.f / (1.f + __expf(-d));

    const int n = n0 + ty, m = m0 + tx;
#pragma unroll 1
    for (int b = 0; b < BATCH; b++) {
        const size_t base = (size_t)b * NN * NN;
        tT[ty][tx] = sc[base + (size_t)(m0 + ty) * NN + (n0 + tx)];
        __syncthreads();
        const float v = 0.5f * (sc[base + (size_t)n * NN + m] + tT[tx][ty]) * a;
        __half hi = __float2half_rn(v);
        __half lo = __float2half_rn(v - __half2float(hi));
        const size_t o1 = base + (size_t)n * NN + m;
        g_Khi[o1] = hi; g_Klo[o1] = lo;
        vS[ty][tx] = v;
        __syncthreads();
        if (m0 != n0) {
            const float vt = vS[tx][ty];
            __half hi2 = __float2half_rn(vt);
            __half lo2 = __float2half_rn(vt - __half2float(hi2));
            const size_t o2 = base + (size_t)(m0 + ty) * NN + (n0 + tx);
            g_Khi[o2] = hi2; g_Klo[o2] = lo2;
        }
        __syncthreads();
    }
}

// ---------------------------------------------------------------------------
// gn_sphere: GroupNorm over (4ch x 2048) per (b,g) then transpose + sphere.
// ---------------------------------------------------------------------------
__global__ __launch_bounds__(256) void gn_sphere(const float* __restrict__ y,
                                                 const float* __restrict__ gw,
                                                 const float* __restrict__ gb)
{
    const int b = blockIdx.x >> 6;
    const int g = blockIdx.x & 63;
    const float* yg = y + ((size_t)b * CC + g * 4) * NN;
    const int tid = threadIdx.x;

    float s = 0.f, s2 = 0.f;
    for (int i = tid; i < 4 * NN; i += 256) { float v = yg[i]; s += v; s2 += v * v; }
    __shared__ float shs[8], shs2[8];
#pragma unroll
    for (int o = 16; o; o >>= 1) {
        s  += __shfl_down_sync(0xffffffffu, s,  o);
        s2 += __shfl_down_sync(0xffffffffu, s2, o);
    }
    if ((tid & 31) == 0) { shs[tid >> 5] = s; shs2[tid >> 5] = s2; }
    __syncthreads();
    if (tid == 0) {
        float ts = 0.f, ts2 = 0.f;
#pragma unroll
        for (int i = 0; i < 8; i++) { ts += shs[i]; ts2 += shs2[i]; }
        shs[0] = ts; shs2[0] = ts2;
    }
    __syncthreads();
    const float mu   = shs[0] * (1.f / (4 * NN));
    const float var  = shs2[0] * (1.f / (4 * NN)) - mu * mu;
    const float rstd = rsqrtf(var + EPS_GN);

    float w[4], bb[4];
#pragma unroll
    for (int j = 0; j < 4; j++) { w[j] = gw[g * 4 + j]; bb[j] = gb[g * 4 + j]; }

    for (int n = tid; n < NN; n += 256) {
        float v[4];
#pragma unroll
        for (int j = 0; j < 4; j++)
            v[j] = (yg[j * NN + n] - mu) * rstd * w[j] + bb[j];
        float n2 = fmaxf(v[0]*v[0] + v[1]*v[1] + v[2]*v[2] + v[3]*v[3], EPS_SPHERE);
        float r = rsqrtf(n2);
        *(float4*)&g_ys[((size_t)b * NN + n) * CC + g * 4] =
            make_float4(v[0]*r, v[1]*r, v[2]*r, v[3]*r);
    }
}

// ---------------------------------------------------------------------------
// sphere_x0: x0 = sphere(x) (fp32) + fp16. One thread per 4-group.
// ---------------------------------------------------------------------------
__global__ __launch_bounds__(256) void sphere_x0(const float* __restrict__ x)
{
    const int idx = blockIdx.x * 256 + threadIdx.x;   // group index
    float4 v = ((const float4*)x)[idx];
    float n2 = fmaxf(v.x*v.x + v.y*v.y + v.z*v.z + v.w*v.w, EPS_SPHERE);
    float rs = rsqrtf(n2);
    float o0 = v.x*rs, o1 = v.y*rs, o2 = v.z*rs, o3 = v.w*rs;
    ((float4*)g_x0)[idx] = make_float4(o0, o1, o2, o3);
    __half2 hh0 = __halves2half2(__float2half_rn(o0), __float2half_rn(o1));
    __half2 hh1 = __halves2half2(__float2half_rn(o2), __float2half_rn(o3));
    ((__half2*)g_xh)[idx * 2]     = hh0;
    ((__half2*)g_xh)[idx * 2 + 1] = hh1;
}

// ---------------------------------------------------------------------------
// step_mma: one Kuramoto step. CTA: M=128 x N=256(full C), K=2048, BK=64.
// 512 threads, 16 warps, warp tile 64x32. 2-term split GEMM: (Khi+Klo) @ x16.
// 3-stage cp.async pipeline, single __syncthreads per chunk.
// ---------------------------------------------------------------------------
#define BK 64
#define OFF_AHI 0
#define OFF_ALO 16384
#define OFF_BHI 32768
#define STAGE   65536
#define NSTAGE  3
#define SMEM_TOTAL (NSTAGE * STAGE)   // 196608
#define CS_STRIDE 264                 // fp32 epilogue staging stride

__global__ __launch_bounds__(512, 1) void step_mma(const float* __restrict__ xc_in,
                                                   float* __restrict__ xout,
                                                   const float* __restrict__ omega,
                                                   const float* __restrict__ gammap)
{
    extern __shared__ __align__(16) char dsm[];
    const uint32_t smem = smem_u32(dsm);
    const int tid  = threadIdx.x;
    const int lane = tid & 31;
    const int wid  = tid >> 5;
    const int wm   = wid & 1;       // warp row (0..1) -> 64 rows each
    const int wn   = wid >> 1;      // warp col (0..7) -> 32 cols each
    const int b    = blockIdx.y;
    const int row0 = blockIdx.x * 128;

    const __half* __restrict__ Ah = g_Khi + (size_t)b * NN * NN + (size_t)row0 * NN;
    const __half* __restrict__ Al = g_Klo + (size_t)b * NN * NN + (size_t)row0 * NN;
    const __half* __restrict__ Bh = g_xh + (size_t)b * NN * CC;

    float acc[4][4][4];             // [mf 16-row][nf 8-col][frag]
#pragma unroll
    for (int i = 0; i < 4; i++)
#pragma unroll
        for (int j = 0; j < 4; j++)
#pragma unroll
            for (int k = 0; k < 4; k++) acc[i][j][k] = 0.f;

    auto load_stage = [&](int chunk, int buf) {
        const uint32_t sb = smem + buf * STAGE;
        const int k0 = chunk * BK;
#pragma unroll
        for (int it = 0; it < 2; it++) {                 // A: 128 rows x 8 chunks
            int idx = tid + it * 512;
            int m = idx >> 3, ck = idx & 7;
            uint32_t off = m * 128 + ((ck ^ (m & 7)) << 4);
            const size_t go = (size_t)m * NN + k0 + ck * 8;
            cp16(sb + OFF_AHI + off, Ah + go);
            cp16(sb + OFF_ALO + off, Al + go);
        }
#pragma unroll
        for (int it = 0; it < 4; it++) {                 // B: 64 k-rows x 32 chunks
            int idx = tid + it * 512;
            int kr = idx >> 5, nc = idx & 31;
            uint32_t off = kr * 512 + ((nc ^ (kr & 7)) << 4);
            const size_t go = (size_t)(k0 + kr) * CC + nc * 8;
            cp16(sb + OFF_BHI + off, Bh + go);
        }
        CP_COMMIT();
    };

    load_stage(0, 0);
    load_stage(1, 1);

#pragma unroll 1
    for (int i = 0; i < 32; i++) {
        const int buf = i - (i / NSTAGE) * NSTAGE;       // i % 3
        if (i < 31) CP_WAIT(1); else CP_WAIT(0);
        __syncthreads();                                 // stage i visible; stage (i+2)%3 free
        if (i + 2 < 32) {
            int nb = (i + 2) - ((i + 2) / NSTAGE) * NSTAGE;
            load_stage(i + 2, nb);
        }

        const uint32_t sA  = smem + buf * STAGE + OFF_AHI;
        const uint32_t sAl = smem + buf * STAGE + OFF_ALO;
        const uint32_t sB  = smem + buf * STAGE + OFF_BHI;

#pragma unroll
        for (int kk = 0; kk < 4; kk++) {
            // B fragments for this warp's 32 columns, k16 slice kk
            uint32_t bh[2][4];
#pragma unroll
            for (int nf2 = 0; nf2 < 2; nf2++) {
                const int kr = kk * 16 + (lane & 15);
                const int nc = wn * 4 + nf2 * 2 + (lane >> 4);
                const uint32_t off = kr * 512 + ((nc ^ (kr & 7)) << 4);
                LDSM_X4T(bh[nf2][0], bh[nf2][1], bh[nf2][2], bh[nf2][3], sB + off);
            }
#pragma unroll
            for (int mf = 0; mf < 4; mf++) {
                const int m = wm * 64 + mf * 16 + (lane & 15);
                const int kc = kk * 2 + (lane >> 4);
                const uint32_t off = m * 128 + ((kc ^ (m & 7)) << 4);
                uint32_t ah0, ah1, ah2, ah3, al0, al1, al2, al3;
                LDSM_X4(ah0, ah1, ah2, ah3, sA  + off);
                LDSM_X4(al0, al1, al2, al3, sAl + off);
#pragma unroll
                for (int nf2 = 0; nf2 < 2; nf2++) {
#pragma unroll
                    for (int j = 0; j < 2; j++) {
                        float* d = acc[mf][nf2 * 2 + j];
                        MMA16816(d, ah0, ah1, ah2, ah3, bh[nf2][j*2], bh[nf2][j*2+1]);
                        MMA16816(d, al0, al1, al2, al3, bh[nf2][j*2], bh[nf2][j*2+1]);
                    }
                }
            }
        }
    }
    __syncthreads();

    // ----- stage acc through smem (reuse stage buffers) -----
    float* cs = (float*)dsm;
#pragma unroll
    for (int mf = 0; mf < 4; mf++)
#pragma unroll
        for (int mh = 0; mh < 2; mh++)
#pragma unroll
            for (int nf = 0; nf < 4; nf++) {
                const int row = wm * 64 + mf * 16 + mh * 8 + (lane >> 2);
                const int col = wn * 32 + nf * 8 + (lane & 3) * 2;
                *(float2*)&cs[row * CS_STRIDE + col] =
                    make_float2(acc[mf][nf][mh * 2], acc[mf][nf][mh * 2 + 1]);
            }
    __syncthreads();

    // ----- fused epilogue: warp w -> rows w*8 .. w*8+7, lane -> 8 cols -----
    const float gamma = *gammap;
    const int c = lane * 8;
    const float og0 = fabsf(omega[(c >> 1) + 0]);
    const float og1 = fabsf(omega[(c >> 1) + 1]);
    const float og2 = fabsf(omega[(c >> 1) + 2]);
    const float og3 = fabsf(omega[(c >> 1) + 3]);
    const float* __restrict__ Xg = (xc_in ? xc_in : g_x0) + (size_t)b * NN * CC;
    const float* __restrict__ Yg = g_ys + (size_t)b * NN * CC;
    float* __restrict__ Og = xout + (size_t)b * NN * CC;
    __half* __restrict__ XHg = g_xh + (size_t)b * NN * CC;

#pragma unroll 1
    for (int rr = 0; rr < 8; rr++) {
        const int lr = wid * 8 + rr;             // local row 0..127
        const size_t goff = (size_t)(row0 + lr) * CC + c;
        float4 k0 = *(const float4*)&cs[lr * CS_STRIDE + c];
        float4 k1 = *(const float4*)&cs[lr * CS_STRIDE + c + 4];
        float4 x0 = *(const float4*)&Xg[goff];
        float4 x1 = *(const float4*)&Xg[goff + 4];
        float4 y0 = *(const float4*)&Yg[goff];
        float4 y1 = *(const float4*)&Yg[goff + 4];

        float ox[8];
        {
            float f0 = k0.x + y0.x, f1 = k0.y + y0.y, f2 = k0.z + y0.z, f3 = k0.w + y0.w;
            float sim = x0.x*f0 + x0.y*f1 + x0.z*f2 + x0.w*f3;
            float d0 =  og0 * x0.y + (f0 - sim * x0.x);
            float d1 = -og0 * x0.x + (f1 - sim * x0.y);
            float d2 =  og1 * x0.w + (f2 - sim * x0.z);
            float d3 = -og1 * x0.z + (f3 - sim * x0.w);
            float u0 = x0.x + gamma * d0, u1 = x0.y + gamma * d1;
            float u2 = x0.z + gamma * d2, u3 = x0.w + gamma * d3;
            float rs = rsqrtf(fmaxf(u0*u0 + u1*u1 + u2*u2 + u3*u3, EPS_SPHERE));
            ox[0] = u0*rs; ox[1] = u1*rs; ox[2] = u2*rs; ox[3] = u3*rs;
        }
        {
            float f0 = k1.x + y1.x, f1 = k1.y + y1.y, f2 = k1.z + y1.z, f3 = k1.w + y1.w;
            float sim = x1.x*f0 + x1.y*f1 + x1.z*f2 + x1.w*f3;
            float d0 =  og2 * x1.y + (f0 - sim * x1.x);
            float d1 = -og2 * x1.x + (f1 - sim * x1.y);
            float d2 =  og3 * x1.w + (f2 - sim * x1.z);
            float d3 = -og3 * x1.z + (f3 - sim * x1.w);
            float u0 = x1.x + gamma * d0, u1 = x1.y + gamma * d1;
            float u2 = x1.z + gamma * d2, u3 = x1.w + gamma * d3;
            float rs = rsqrtf(fmaxf(u0*u0 + u1*u1 + u2*u2 + u3*u3, EPS_SPHERE));
            ox[4] = u0*rs; ox[5] = u1*rs; ox[6] = u2*rs; ox[7] = u3*rs;
        }
        *(float4*)&Og[goff]     = make_float4(ox[0], ox[1], ox[2], ox[3]);
        *(float4*)&Og[goff + 4] = make_float4(ox[4], ox[5], ox[6], ox[7]);

        uint32_t hw[4];
#pragma unroll
        for (int j = 0; j < 4; j++) {
            __half2 p = __halves2half2(__float2half_rn(ox[2*j]), __float2half_rn(ox[2*j+1]));
            hw[j] = *(uint32_t*)&p;
        }
        *(uint4*)&XHg[goff] = make_uint4(hw[0], hw[1], hw[2], hw[3]);
    }
}

// ---------------------------------------------------------------------------
// Launch. Inputs: x, y, sc, U, omega_param, gn_w, gn_b, gamma, Q.
// Output: xs [Q=8, B, N, C] fp32.
// ---------------------------------------------------------------------------
extern "C" void kernel_launch(void* const* d_in, const int* in_sizes, int n_in,
                              void* d_out, int out_size)
{
    const float* x     = (const float*)d_in[0];
    const float* y     = (const float*)d_in[1];
    const float* sc    = (const float*)d_in[2];
    const float* U     = (const float*)d_in[3];
    const float* omega = (const float*)d_in[4];
    const float* gw    = (const float*)d_in[5];
    const float* gb    = (const float*)d_in[6];
    const float* gamma = (const float*)d_in[7];
    float* out = (float*)d_out;

    static int attr_set = 0;
    if (!attr_set) {
        cudaFuncSetAttribute(step_mma, cudaFuncAttributeMaxDynamicSharedMemorySize,
                             SMEM_TOTAL);
        attr_set = 1;
    }

    prep_K<<<dim3(NN / 32, NN / 32), dim3(32, 32)>>>(sc, U);
    gn_sphere<<<BATCH * 64, 256>>>(y, gw, gb);
    sphere_x0<<<(BATCH * NN * CC / 4) / 256, 256>>>(x);

    const size_t step_elems = (size_t)BATCH * NN * CC;
    for (int q = 0; q < QSTEPS; q++) {
        const float* xc = (q == 0) ? nullptr : out + (size_t)(q - 1) * step_elems;
        step_mma<<<dim3(16, BATCH), 512, SMEM_TOTAL>>>(xc, out + (size_t)q * step_elems,
                                                       omega, gamma);
    }
}